// round 5
// baseline (speedup 1.0000x reference)
#include <cuda_runtime.h>
#include <stdint.h>

#define ATT     1024
#define GM1     14          // groups actually written (G-1)
#define LP1     16          // rows per class
#define GSIZE   64
#define NCLASS  6000
#define NUNSEEN 1200
#define NSEEN   4800

#define A_TILE  128         // attrs per write tile
#define C_TILE  16          // classes per write tile

#define WBLK_GZSL ((NCLASS  / C_TILE) * (ATT / A_TILE))   // 375*8 = 3000
#define WBLK_SEEN ((NSEEN   / C_TILE) * (ATT / A_TILE))   // 300*8 = 2400
#define WBLK_ZSL  ((NUNSEEN / C_TILE) * (ATT / A_TILE))   // 75*8  = 600
#define WBLK_TOTAL (WBLK_GZSL + WBLK_SEEN + WBLK_ZSL)     // 6000

// Persistent scratch (allocation-free)
__device__ uint32_t g_colmask[ATT];
__device__ float    g_inv[NCLASS * LP1];

// ---------------------------------------------------------------------------
// Kernel 1: per-class inverse norms. One block per class. Each block rebuilds
// the column-group mask locally in smem (ballot-based distinct counts — no
// same-address atomic storm). Block 0 publishes g_colmask for the writer.
// ---------------------------------------------------------------------------
__global__ void __launch_bounds__(256) k_norm(
    const float* __restrict__ attr,
    const float* __restrict__ betas,
    const int*   __restrict__ group_cols)
{
    __shared__ uint32_t s_mask[ATT];
    __shared__ int      s_cnt[GM1];
    __shared__ float    s_cb2[GM1];
    __shared__ float    s_red[8][15];

    const int c    = blockIdx.x;
    const int t    = threadIdx.x;
    const int w    = t >> 5;
    const int lane = t & 31;

#pragma unroll
    for (int i = 0; i < 4; ++i) s_mask[i * 256 + t] = 0u;
    if (t < GM1) s_cnt[t] = 0;
    __syncthreads();

    for (int i = t; i < GM1 * GSIZE; i += 256) {
        int col = __ldg(group_cols + i);
        atomicOr(&s_mask[col], 1u << ((i >> 6) + 2));
    }
    __syncthreads();

    // distinct counts via ballots
#pragma unroll
    for (int i = 0; i < 4; ++i) {
        uint32_t m = s_mask[i * 256 + t];
#pragma unroll
        for (int g = 0; g < GM1; ++g) {
            uint32_t bal = __ballot_sync(0xffffffffu, m & (1u << (g + 2)));
            if (lane == 0 && bal) atomicAdd(&s_cnt[g], __popc(bal));
        }
    }
    __syncthreads();
    if (t < GM1) {
        float b = __ldg(betas + t);
        s_cb2[t] = (float)s_cnt[t] * b * b;
    }
    if (c == 0) {
#pragma unroll
        for (int i = 0; i < 4; ++i) g_colmask[i * 256 + t] = s_mask[i * 256 + t];
    }
    __syncthreads();

    // single streaming pass over this class's row
    const float* row = attr + (size_t)c * ATT;
    float tot = 0.f;
    float gs[GM1];
#pragma unroll
    for (int g = 0; g < GM1; ++g) gs[g] = 0.f;
#pragma unroll
    for (int it = 0; it < 4; ++it) {
        int a = t + it * 256;
        float v  = __ldg(row + a);
        float v2 = v * v;
        tot += v2;
        uint32_t m = s_mask[a];
#pragma unroll
        for (int g = 0; g < GM1; ++g)
            if (m & (1u << (g + 2))) gs[g] += v2;
    }
#pragma unroll
    for (int o = 16; o; o >>= 1) {
        tot += __shfl_xor_sync(0xffffffffu, tot, o);
#pragma unroll
        for (int g = 0; g < GM1; ++g)
            gs[g] += __shfl_xor_sync(0xffffffffu, gs[g], o);
    }
    if (lane == 0) {
        s_red[w][0] = tot;
#pragma unroll
        for (int g = 0; g < GM1; ++g) s_red[w][g + 1] = gs[g];
    }
    __syncthreads();
    if (t < LP1) {
        float tt = 0.f;
#pragma unroll
        for (int w2 = 0; w2 < 8; ++w2) tt += s_red[w2][0];
        float x;
        if (t < 2) {
            x = tt;
        } else {
            float gsum = 0.f;
#pragma unroll
            for (int w2 = 0; w2 < 8; ++w2) gsum += s_red[w2][t - 1];
            x = tt - gsum + s_cb2[t - 2];
        }
        g_inv[c * LP1 + t] = 1.0f / fmaxf(sqrtf(x), 1e-12f);
    }
}

// ---------------------------------------------------------------------------
// Kernel 2: fused streaming writer. Tile = 16 classes x 128 attrs; 256 thr.
// Per block: ~10.5 KB loads -> 128 KB of contiguous 512B streaming stores.
// Consecutive blocks cover adjacent class-chunks of the same attr rows.
// ---------------------------------------------------------------------------
__global__ void __launch_bounds__(256) k_write(
    const float* __restrict__ attr,
    const float* __restrict__ betas,
    const int*   __restrict__ unseen,
    const int*   __restrict__ seen,
    float* __restrict__ out)
{
    int b = blockIdx.x;
    const int* map;
    int nclass;
    float* obaseseg;
    if (b < WBLK_GZSL) {
        map = nullptr; nclass = NCLASS;
        obaseseg = out + (size_t)ATT * (NUNSEEN + NSEEN) * LP1;
    } else if (b < WBLK_GZSL + WBLK_SEEN) {
        b -= WBLK_GZSL;
        map = seen; nclass = NSEEN;
        obaseseg = out + (size_t)ATT * NUNSEEN * LP1;
    } else {
        b -= WBLK_GZSL + WBLK_SEEN;
        map = unseen; nclass = NUNSEEN;
        obaseseg = out;
    }
    const int c_tiles = nclass / C_TILE;
    const int c0 = (b % c_tiles) * C_TILE;
    const int a0 = (b / c_tiles) * A_TILE;
    const int stride = nclass * LP1;

    __shared__ float    s_attr[C_TILE][A_TILE + 1];  // 8.25 KB
    __shared__ float    s_inv [C_TILE][LP1 + 1];
    __shared__ uint32_t s_cm  [A_TILE];
    __shared__ float    s_beta[LP1];
    __shared__ int      s_cls [C_TILE];

    const int t    = threadIdx.x;
    const int w    = t >> 5;
    const int lane = t & 31;

    if (t < C_TILE)              s_cls[t] = map ? __ldg(map + c0 + t) : (c0 + t);
    if (t >= 16 && t < 32)       s_beta[t - 16] = (t - 16 < 2) ? 0.f : __ldg(betas + (t - 16) - 2);
    if (t >= 128)                s_cm[t - 128] = g_colmask[a0 + (t - 128)];
    __syncthreads();

    // attr tile: 16 rows x 128 floats = 512 float4; 2 per thread
#pragma unroll
    for (int i = 0; i < 2; ++i) {
        int idx = i * 256 + t;
        int ci  = idx >> 5;            // 0..15
        int j   = idx & 31;            // float4 within 128-float row
        float4 v = __ldg((const float4*)(attr + (size_t)s_cls[ci] * ATT + a0) + j);
        s_attr[ci][j * 4 + 0] = v.x; s_attr[ci][j * 4 + 1] = v.y;
        s_attr[ci][j * 4 + 2] = v.z; s_attr[ci][j * 4 + 3] = v.w;
    }
    if (t < 64) {                      // inv tile: 16 x 16 floats
        int ci = t >> 2, q2 = t & 3;
        float4 v = *(const float4*)(g_inv + (size_t)s_cls[ci] * LP1 + q2 * 4);
        s_inv[ci][q2 * 4 + 0] = v.x; s_inv[ci][q2 * 4 + 1] = v.y;
        s_inv[ci][q2 * 4 + 2] = v.z; s_inv[ci][q2 * 4 + 3] = v.w;
    }
    __syncthreads();

    // store phase: lane -> (ci0 = lane>>2 in 0..7, q = lane&3);
    // cc in {0,1} selects class half; warp wave = 512B contiguous.
    const int ci0 = lane >> 2;
    const int q   = lane & 3;
    const int ciA = ci0, ciB = ci0 + 8;

    const float b0 = s_beta[4 * q + 0], b1 = s_beta[4 * q + 1];
    const float b2 = s_beta[4 * q + 2], b3 = s_beta[4 * q + 3];

    const float iA0 = s_inv[ciA][4 * q + 0], iA1 = s_inv[ciA][4 * q + 1];
    const float iA2 = s_inv[ciA][4 * q + 2], iA3 = s_inv[ciA][4 * q + 3];
    const float iB0 = s_inv[ciB][4 * q + 0], iB1 = s_inv[ciB][4 * q + 1];
    const float iB2 = s_inv[ciB][4 * q + 2], iB3 = s_inv[ciB][4 * q + 3];
    const float bA0 = b0 * iA0, bA1 = b1 * iA1, bA2 = b2 * iA2, bA3 = b3 * iA3;
    const float bB0 = b0 * iB0, bB1 = b1 * iB1, bB2 = b2 * iB2, bB3 = b3 * iB3;

    float* obA = obaseseg + (size_t)(c0 + ciA) * LP1 + 4 * q;
    float* obB = obaseseg + (size_t)(c0 + ciB) * LP1 + 4 * q;

#pragma unroll 4
    for (int i = 0; i < A_TILE / 8; ++i) {        // 16 iterations
        int al = i * 8 + w;
        size_t rowoff = (size_t)(a0 + al) * stride;
        uint32_t m = s_cm[al] >> (4 * q);
        float avA = s_attr[ciA][al];
        float avB = s_attr[ciB][al];
        float4 vA, vB;
        vA.x = (m & 1u) ? bA0 : avA * iA0;
        vA.y = (m & 2u) ? bA1 : avA * iA1;
        vA.z = (m & 4u) ? bA2 : avA * iA2;
        vA.w = (m & 8u) ? bA3 : avA * iA3;
        vB.x = (m & 1u) ? bB0 : avB * iB0;
        vB.y = (m & 2u) ? bB1 : avB * iB1;
        vB.z = (m & 4u) ? bB2 : avB * iB2;
        vB.w = (m & 8u) ? bB3 : avB * iB3;
        __stcs((float4*)(obA + rowoff), vA);
        __stcs((float4*)(obB + rowoff), vB);
    }
}

// ---------------------------------------------------------------------------
extern "C" void kernel_launch(void* const* d_in, const int* in_sizes, int n_in,
                              void* d_out, int out_size) {
    const float* attribute  = (const float*)d_in[0];
    const float* betas      = (const float*)d_in[1];
    const int*   group_cols = (const int*)d_in[2];
    const int*   unseen     = (const int*)d_in[3];
    const int*   seen       = (const int*)d_in[4];
    float* out = (float*)d_out;

    k_norm<<<NCLASS, 256>>>(attribute, betas, group_cols);
    k_write<<<WBLK_TOTAL, 256>>>(attribute, betas, unseen, seen, out);
}

// round 6
// speedup vs baseline: 1.2316x; 1.2316x over previous
#include <cuda_runtime.h>
#include <stdint.h>

#define ATT     1024
#define GM1     14          // groups actually written (G-1)
#define LP1     16          // rows per class
#define GSIZE   64
#define NCLASS  6000
#define NUNSEEN 1200
#define NSEEN   4800

#define A_TILE  128         // attrs per write tile
#define C_TILE  16          // classes per write tile

#define WBLK_GZSL ((NCLASS  / C_TILE) * (ATT / A_TILE))   // 3000
#define WBLK_SEEN ((NSEEN   / C_TILE) * (ATT / A_TILE))   // 2400
#define WBLK_ZSL  ((NUNSEEN / C_TILE) * (ATT / A_TILE))   // 600
#define WBLK_TOTAL (WBLK_GZSL + WBLK_SEEN + WBLK_ZSL)     // 6000

// Persistent scratch (allocation-free)
__device__ uint32_t g_colmask[ATT];
__device__ float    g_cb2[GM1];          // distinct_count_g * beta_g^2
__device__ float    g_inv[NCLASS * LP1];

// ---------------------------------------------------------------------------
// Kernel 1: column membership mask + distinct counts. One block, 1024 thr.
// Ballot-based counting: 32 warps x 14 groups = 448 smem atomics total.
// ---------------------------------------------------------------------------
__global__ void __launch_bounds__(1024) k_mask(
    const int*   __restrict__ group_cols,
    const float* __restrict__ betas)
{
    __shared__ uint32_t s_mask[ATT];
    __shared__ int      s_cnt[GM1];
    const int t    = threadIdx.x;
    const int lane = t & 31;

    s_mask[t] = 0u;
    if (t < GM1) s_cnt[t] = 0;
    __syncthreads();
    if (t < GM1 * GSIZE) {
        int col = __ldg(group_cols + t);
        atomicOr(&s_mask[col], 1u << ((t >> 6) + 2));
    }
    __syncthreads();
    uint32_t m = s_mask[t];
    g_colmask[t] = m;
#pragma unroll
    for (int g = 0; g < GM1; ++g) {
        uint32_t bal = __ballot_sync(0xffffffffu, m & (1u << (g + 2)));
        if (lane == 0 && bal) atomicAdd(&s_cnt[g], __popc(bal));
    }
    __syncthreads();
    if (t < GM1) {
        float b = __ldg(betas + t);
        g_cb2[t] = (float)s_cnt[t] * b * b;
    }
}

// ---------------------------------------------------------------------------
// Kernel 2: per-class inverse norms. One block per class; mask from L2.
// ---------------------------------------------------------------------------
__global__ void __launch_bounds__(256) k_norm(const float* __restrict__ attr) {
    const int c    = blockIdx.x;
    const int t    = threadIdx.x;
    const int w    = t >> 5;
    const int lane = t & 31;
    const float* row = attr + (size_t)c * ATT;

    float tot = 0.f;
    float gs[GM1];
#pragma unroll
    for (int g = 0; g < GM1; ++g) gs[g] = 0.f;

#pragma unroll
    for (int it = 0; it < 4; ++it) {
        int a = t + it * 256;
        float v  = __ldg(row + a);
        float v2 = v * v;
        tot += v2;
        uint32_t m = g_colmask[a];
#pragma unroll
        for (int g = 0; g < GM1; ++g)
            if (m & (1u << (g + 2))) gs[g] += v2;
    }

#pragma unroll
    for (int o = 16; o; o >>= 1) {
        tot += __shfl_xor_sync(0xffffffffu, tot, o);
#pragma unroll
        for (int g = 0; g < GM1; ++g)
            gs[g] += __shfl_xor_sync(0xffffffffu, gs[g], o);
    }

    __shared__ float s_red[8][15];
    if (lane == 0) {
        s_red[w][0] = tot;
#pragma unroll
        for (int g = 0; g < GM1; ++g) s_red[w][g + 1] = gs[g];
    }
    __syncthreads();

    if (t < LP1) {
        float tt = 0.f;
#pragma unroll
        for (int w2 = 0; w2 < 8; ++w2) tt += s_red[w2][0];
        float x;
        if (t < 2) {
            x = tt;
        } else {
            float gsum = 0.f;
#pragma unroll
            for (int w2 = 0; w2 < 8; ++w2) gsum += s_red[w2][t - 1];
            x = tt - gsum + g_cb2[t - 2];
        }
        g_inv[c * LP1 + t] = 1.0f / fmaxf(sqrtf(x), 1e-12f);
    }
}

// ---------------------------------------------------------------------------
// Kernel 3: fused streaming writer. Tile = 16 classes x 128 attrs; 256 thr.
// min 8 blocks/SM forces regs <= 32 for full occupancy; select-then-multiply
// keeps register count low. Warp wave = 512B contiguous streaming stores.
// ---------------------------------------------------------------------------
__global__ void __launch_bounds__(256, 8) k_write(
    const float* __restrict__ attr,
    const float* __restrict__ betas,
    const int*   __restrict__ unseen,
    const int*   __restrict__ seen,
    float* __restrict__ out)
{
    int b = blockIdx.x;
    const int* map;
    int nclass;
    float* obaseseg;
    if (b < WBLK_GZSL) {
        map = nullptr; nclass = NCLASS;
        obaseseg = out + (size_t)ATT * (NUNSEEN + NSEEN) * LP1;
    } else if (b < WBLK_GZSL + WBLK_SEEN) {
        b -= WBLK_GZSL;
        map = seen; nclass = NSEEN;
        obaseseg = out + (size_t)ATT * NUNSEEN * LP1;
    } else {
        b -= WBLK_GZSL + WBLK_SEEN;
        map = unseen; nclass = NUNSEEN;
        obaseseg = out;
    }
    const int c_tiles = nclass / C_TILE;
    const int c0 = (b % c_tiles) * C_TILE;
    const int a0 = (b / c_tiles) * A_TILE;
    const int stride = nclass * LP1;

    __shared__ float    s_attr[C_TILE][A_TILE + 1];  // 8.25 KB
    __shared__ float    s_inv [C_TILE][LP1 + 1];
    __shared__ uint32_t s_cm  [A_TILE];
    __shared__ float    s_beta[LP1];
    __shared__ int      s_cls [C_TILE];

    const int t    = threadIdx.x;
    const int w    = t >> 5;
    const int lane = t & 31;

    if (t < C_TILE)        s_cls[t] = map ? __ldg(map + c0 + t) : (c0 + t);
    if (t >= 16 && t < 32) s_beta[t - 16] = (t - 16 < 2) ? 0.f : __ldg(betas + (t - 16) - 2);
    if (t >= 128)          s_cm[t - 128] = g_colmask[a0 + (t - 128)];
    __syncthreads();

    // attr tile: 16 rows x 128 floats = 512 float4; 2 per thread
#pragma unroll
    for (int i = 0; i < 2; ++i) {
        int idx = i * 256 + t;
        int ci  = idx >> 5;
        int j   = idx & 31;
        float4 v = __ldg((const float4*)(attr + (size_t)s_cls[ci] * ATT + a0) + j);
        s_attr[ci][j * 4 + 0] = v.x; s_attr[ci][j * 4 + 1] = v.y;
        s_attr[ci][j * 4 + 2] = v.z; s_attr[ci][j * 4 + 3] = v.w;
    }
    if (t < 64) {
        int ci = t >> 2, q2 = t & 3;
        float4 v = *(const float4*)(g_inv + (size_t)s_cls[ci] * LP1 + q2 * 4);
        s_inv[ci][q2 * 4 + 0] = v.x; s_inv[ci][q2 * 4 + 1] = v.y;
        s_inv[ci][q2 * 4 + 2] = v.z; s_inv[ci][q2 * 4 + 3] = v.w;
    }
    __syncthreads();

    // store phase: lane -> (ci0 in 0..7, q in 0..3); classes ci0 and ci0+8.
    const int ci0 = lane >> 2;
    const int q   = lane & 3;
    const int ciA = ci0, ciB = ci0 + 8;

    const float b0 = s_beta[4 * q + 0], b1 = s_beta[4 * q + 1];
    const float b2 = s_beta[4 * q + 2], b3 = s_beta[4 * q + 3];
    const float iA0 = s_inv[ciA][4 * q + 0], iA1 = s_inv[ciA][4 * q + 1];
    const float iA2 = s_inv[ciA][4 * q + 2], iA3 = s_inv[ciA][4 * q + 3];
    const float iB0 = s_inv[ciB][4 * q + 0], iB1 = s_inv[ciB][4 * q + 1];
    const float iB2 = s_inv[ciB][4 * q + 2], iB3 = s_inv[ciB][4 * q + 3];

    float* obA = obaseseg + (size_t)(c0 + ciA) * LP1 + 4 * q;
    float* obB = obaseseg + (size_t)(c0 + ciB) * LP1 + 4 * q;

#pragma unroll 2
    for (int i = 0; i < A_TILE / 8; ++i) {        // 16 iterations
        int al = i * 8 + w;
        size_t rowoff = (size_t)(a0 + al) * stride;
        uint32_t m = s_cm[al] >> (4 * q);
        float avA = s_attr[ciA][al];
        float avB = s_attr[ciB][al];
        float4 vA, vB;
        vA.x = ((m & 1u) ? b0 : avA) * iA0;
        vA.y = ((m & 2u) ? b1 : avA) * iA1;
        vA.z = ((m & 4u) ? b2 : avA) * iA2;
        vA.w = ((m & 8u) ? b3 : avA) * iA3;
        vB.x = ((m & 1u) ? b0 : avB) * iB0;
        vB.y = ((m & 2u) ? b1 : avB) * iB1;
        vB.z = ((m & 4u) ? b2 : avB) * iB2;
        vB.w = ((m & 8u) ? b3 : avB) * iB3;
        __stcs((float4*)(obA + rowoff), vA);
        __stcs((float4*)(obB + rowoff), vB);
    }
}

// ---------------------------------------------------------------------------
extern "C" void kernel_launch(void* const* d_in, const int* in_sizes, int n_in,
                              void* d_out, int out_size) {
    const float* attribute  = (const float*)d_in[0];
    const float* betas      = (const float*)d_in[1];
    const int*   group_cols = (const int*)d_in[2];
    const int*   unseen     = (const int*)d_in[3];
    const int*   seen       = (const int*)d_in[4];
    float* out = (float*)d_out;

    k_mask<<<1, 1024>>>(group_cols, betas);
    k_norm<<<NCLASS, 256>>>(attribute);
    k_write<<<WBLK_TOTAL, 256>>>(attribute, betas, unseen, seen, out);
}

// round 7
// speedup vs baseline: 1.3281x; 1.0784x over previous
#include <cuda_runtime.h>
#include <stdint.h>

#define ATT     1024
#define GM1     14          // groups actually written (G-1)
#define LP1     16          // rows per class
#define GSIZE   64
#define NCLASS  6000
#define NUNSEEN 1200
#define NSEEN   4800
#define CPB     4           // classes per block (full attr row per block)

#define BLK_GZSL (NCLASS  / CPB)   // 1500
#define BLK_SEEN (NSEEN   / CPB)   // 1200
#define BLK_ZSL  (NUNSEEN / CPB)   // 300
#define BLK_TOTAL (BLK_GZSL + BLK_SEEN + BLK_ZSL)  // 3000

// ---------------------------------------------------------------------------
// Single fused kernel. Per block: 4 classes x 1024 attrs.
//   Phase 1: rebuild column mask (L2-resident group_cols) + stage 4 attr rows
//   Phase 2: ballot distinct-counts -> cnt*beta^2
//   Phase 3: warps 0-3 compute the 4x16 inverse norms from smem
//   Phase 4: 256 KB of contiguous streaming stores (dominates block lifetime)
// 8 blocks/SM (20.7 KB smem, regs <= 32) so prologues hide under other
// blocks' store streams.
// ---------------------------------------------------------------------------
__global__ void __launch_bounds__(256, 8) k_all(
    const float* __restrict__ attr,
    const float* __restrict__ betas,
    const int*   __restrict__ group_cols,
    const int*   __restrict__ unseen,
    const int*   __restrict__ seen,
    float* __restrict__ out)
{
    // ---- segment decode (largest first) ----
    int b = blockIdx.x;
    const int* map;
    int nclass;
    float* obaseseg;
    if (b < BLK_GZSL) {
        map = nullptr; nclass = NCLASS;
        obaseseg = out + (size_t)ATT * (NUNSEEN + NSEEN) * LP1;
    } else if (b < BLK_GZSL + BLK_SEEN) {
        b -= BLK_GZSL;
        map = seen; nclass = NSEEN;
        obaseseg = out + (size_t)ATT * NUNSEEN * LP1;
    } else {
        b -= BLK_GZSL + BLK_SEEN;
        map = unseen; nclass = NUNSEEN;
        obaseseg = out;
    }
    const int c0 = b * CPB;
    const int stride = nclass * LP1;

    __shared__ float    s_attr[CPB][ATT];       // 16 KB
    __shared__ uint32_t s_mask[ATT];            // 4 KB
    __shared__ float    s_inv [CPB][LP1];
    __shared__ float    s_beta[LP1];
    __shared__ float    s_cb2 [GM1];
    __shared__ int      s_cnt [GM1];
    __shared__ int      s_cls [CPB];

    const int t    = threadIdx.x;
    const int w    = t >> 5;
    const int lane = t & 31;

    // ---- init ----
#pragma unroll
    for (int i = 0; i < 4; ++i) s_mask[i * 256 + t] = 0u;
    if (t < GM1)              s_cnt[t] = 0;
    if (t < CPB)              s_cls[t] = map ? __ldg(map + c0 + t) : (c0 + t);
    if (t >= 16 && t < 32)    s_beta[t - 16] = (t < 18) ? 0.f : __ldg(betas + t - 18);
    __syncthreads();

    // ---- mask rebuild (896 entries, strided) + attr tile (1024 float4) ----
    for (int i = t; i < GM1 * GSIZE; i += 256) {
        int col = __ldg(group_cols + i);
        atomicOr(&s_mask[col], 1u << ((i >> 6) + 2));
    }
#pragma unroll
    for (int i = 0; i < 4; ++i) {
        int idx = i * 256 + t;            // 0..1023 float4 slots
        int ci  = idx >> 8;               // class 0..3
        int j   = idx & 255;              // float4 within row
        float4 v = __ldg((const float4*)(attr + (size_t)s_cls[ci] * ATT) + j);
        s_attr[ci][j * 4 + 0] = v.x; s_attr[ci][j * 4 + 1] = v.y;
        s_attr[ci][j * 4 + 2] = v.z; s_attr[ci][j * 4 + 3] = v.w;
    }
    __syncthreads();

    // ---- distinct counts via ballots ----
#pragma unroll
    for (int i = 0; i < 4; ++i) {
        uint32_t m = s_mask[i * 256 + t];
#pragma unroll
        for (int g = 0; g < GM1; ++g) {
            uint32_t bal = __ballot_sync(0xffffffffu, m & (1u << (g + 2)));
            if (lane == 0 && bal) atomicAdd(&s_cnt[g], __popc(bal));
        }
    }
    __syncthreads();
    if (t < GM1) s_cb2[t] = (float)s_cnt[t] * s_beta[t + 2] * s_beta[t + 2];
    __syncthreads();

    // ---- per-class inverse norms: warp w (w<4) handles class w ----
    if (w < CPB) {
        float tot = 0.f;
        float gs[GM1];
#pragma unroll
        for (int g = 0; g < GM1; ++g) gs[g] = 0.f;
#pragma unroll
        for (int j = 0; j < 32; ++j) {
            int a = j * 32 + lane;
            float v  = s_attr[w][a];
            float v2 = v * v;
            tot += v2;
            uint32_t m = s_mask[a];
#pragma unroll
            for (int g = 0; g < GM1; ++g)
                if (m & (1u << (g + 2))) gs[g] += v2;
        }
#pragma unroll
        for (int o = 16; o; o >>= 1) {
            tot += __shfl_xor_sync(0xffffffffu, tot, o);
#pragma unroll
            for (int g = 0; g < GM1; ++g)
                gs[g] += __shfl_xor_sync(0xffffffffu, gs[g], o);
        }
        // lane l computes layer l's inverse norm; needs gs[l-2] -> shuffle
        // simpler: lane 0 owns all values; broadcast via smem
        if (lane == 0) {
            s_inv[w][0] = tot;            // stash raw sums temporarily
#pragma unroll
            for (int g = 0; g < GM1; ++g) s_inv[w][g + 2] = gs[g];
            s_inv[w][1] = tot;
        }
        __syncwarp();
        if (lane < LP1) {
            float tt = s_inv[w][0];
            float x  = (lane < 2) ? tt
                                  : tt - s_inv[w][lane] + s_cb2[lane - 2];
            // note: s_inv[w][lane] currently holds gs[lane-2] for lane>=2
            s_inv[w][lane] = 1.0f / fmaxf(sqrtf(x), 1e-12f);
        }
    }
    __syncthreads();

    // ---- streaming transposed write ----
    // lane: half = lane>>4 (attr row parity), ci = (lane>>2)&3, q = lane&3.
    // Warp wave: two 256B contiguous segments (rows a, a+1), full 128B lines.
    const int half = lane >> 4;
    const int ci   = (lane >> 2) & 3;
    const int q    = lane & 3;

    const float b0 = s_beta[4 * q + 0], b1 = s_beta[4 * q + 1];
    const float b2 = s_beta[4 * q + 2], b3 = s_beta[4 * q + 3];
    const float i0 = s_inv[ci][4 * q + 0], i1 = s_inv[ci][4 * q + 1];
    const float i2 = s_inv[ci][4 * q + 2], i3 = s_inv[ci][4 * q + 3];

    float* ob = obaseseg + (size_t)(c0 + ci) * LP1 + 4 * q;
    const float* arow = s_attr[ci];
    const int abase = (w << 1) + half;    // 0..15

#pragma unroll 4
    for (int it = 0; it < ATT / 16; ++it) {   // 64 iterations
        int a = it * 16 + abase;
        uint32_t m = s_mask[a] >> (4 * q);
        float av = arow[a];
        float4 v;
        v.x = ((m & 1u) ? b0 : av) * i0;
        v.y = ((m & 2u) ? b1 : av) * i1;
        v.z = ((m & 4u) ? b2 : av) * i2;
        v.w = ((m & 8u) ? b3 : av) * i3;
        __stcs((float4*)(ob + (size_t)a * stride), v);
    }
}

// ---------------------------------------------------------------------------
extern "C" void kernel_launch(void* const* d_in, const int* in_sizes, int n_in,
                              void* d_out, int out_size) {
    const float* attribute  = (const float*)d_in[0];
    const float* betas      = (const float*)d_in[1];
    const int*   group_cols = (const int*)d_in[2];
    const int*   unseen     = (const int*)d_in[3];
    const int*   seen       = (const int*)d_in[4];
    float* out = (float*)d_out;

    k_all<<<BLK_TOTAL, 256>>>(attribute, betas, group_cols, unseen, seen, out);
}